// round 8
// baseline (speedup 1.0000x reference)
#include <cuda_runtime.h>
#include <math.h>

#define NN 256
#define MM 1024
#define CC 64
#define KK 16

// ------------------------- scratch (device globals) -------------------------
__device__ float g_xyz[NN*3];
__device__ float g_rfi[MM*3];
__device__ float g_snormT[CC*NN];   // normalized warped_points, [c][n]
__device__ float g_dnorm[MM*CC];    // normalized rf, [m][c]
__device__ float g_sim[MM*NN];
__device__ float g_rowmax[MM];
__device__ float g_colmax[NN];
__device__ int   g_knn[NN*KK];
__device__ float g_pcnT[CC*NN];     // normalized pc_feats, [c][n]
__device__ float g_imgn[MM*CC];     // normalized img_feats, [m][c]
__device__ float g_sim2[MM*NN];
__device__ float g_rowmax2[MM];
__device__ float g_colmax2[NN];
__device__ float g_A[NN*128];       // per-n partial of layer-1
__device__ float g_CmatT[128*MM];   // per-m partial of layer-1 (+bias), [j][m]
__device__ float g_feats[NN*MM*CC]; // 64 MB, post-MLP features
__device__ float g_z[NN*MM];        // max over c of feats
__device__ float g_uv[NN*2];
__device__ float g_win[NN];

// ------------- prep: xyz scale, l2norm of warped_points / rf ----------------
__global__ void k_prep(const float* __restrict__ wxyz, const float* __restrict__ wpts,
                       const float* __restrict__ RF3, const float* __restrict__ RF3i,
                       const float* __restrict__ lz) {
    __shared__ float red[2];
    int b = blockIdx.x, t = threadIdx.x;   // 64 threads
    float v;
    if (b < NN) v = wpts[b*CC + t];
    else        v = RF3[t*MM + (b - NN)];
    float ss = v*v;
    #pragma unroll
    for (int o = 16; o; o >>= 1) ss += __shfl_xor_sync(0xffffffffu, ss, o);
    if ((t & 31) == 0) red[t >> 5] = ss;
    __syncthreads();
    float nrm = fmaxf(sqrtf(red[0] + red[1]), 1e-12f);
    if (b < NN) {
        g_snormT[t*NN + b] = v / nrm;
        if (t < 3) g_xyz[b*3 + t] = wxyz[b*3 + t] * lz[b];
    } else {
        int m = b - NN;
        g_dnorm[m*CC + t] = v / nrm;
        if (t < 3) g_rfi[m*3 + t] = RF3i[t*MM + m];
    }
}

// ------------------- cosine sim matrix + row max (over n) -------------------
__global__ void k_simmat(int which) {
    const float* dn  = which ? g_imgn : g_dnorm;
    const float* snT = which ? g_pcnT : g_snormT;
    float* sim  = which ? g_sim2    : g_sim;
    float* rmax = which ? g_rowmax2 : g_rowmax;
    __shared__ float dvec[CC];
    __shared__ float red[8];
    int m = blockIdx.x, t = threadIdx.x;   // 256 threads: t = n
    if (t < CC) dvec[t] = dn[m*CC + t];
    __syncthreads();
    float acc = 0.f;
    #pragma unroll 8
    for (int c = 0; c < CC; c++) acc += dvec[c] * snT[c*NN + t];
    sim[m*NN + t] = acc;
    float mx = acc;
    #pragma unroll
    for (int o = 16; o; o >>= 1) mx = fmaxf(mx, __shfl_xor_sync(0xffffffffu, mx, o));
    if ((t & 31) == 0) red[t >> 5] = mx;
    __syncthreads();
    if (t == 0) {
        float r = red[0];
        #pragma unroll
        for (int i = 1; i < 8; i++) r = fmaxf(r, red[i]);
        rmax[m] = r;
    }
}

// -------------------------- column max (over m) -----------------------------
__global__ void k_colmax(int which) {
    const float* sim = which ? g_sim2 : g_sim;
    float* cm = which ? g_colmax2 : g_colmax;
    __shared__ float red[256];
    int n = blockIdx.x, t = threadIdx.x;
    float mx = -1e30f;
    for (int m = t; m < MM; m += 256) mx = fmaxf(mx, sim[m*NN + n]);
    red[t] = mx; __syncthreads();
    for (int s = 128; s > 0; s >>= 1) { if (t < s) red[t] = fmaxf(red[t], red[t+s]); __syncthreads(); }
    if (t == 0) cm[n] = red[0];
}

// --------------- KNN rank-select (matches top_k tie-break) ------------------
__global__ void k_knn() {
    __shared__ float sx[NN*3];
    __shared__ float sd[NN];
    int n = blockIdx.x, t = threadIdx.x;   // 256
    for (int i = t; i < NN*3; i += 256) sx[i] = g_xyz[i];
    __syncthreads();
    float dx = sx[t*3+0]-sx[n*3+0];
    float dy = sx[t*3+1]-sx[n*3+1];
    float dz = sx[t*3+2]-sx[n*3+2];
    float d2 = dx*dx + dy*dy + dz*dz;
    sd[t] = d2; __syncthreads();
    int cnt = 0;
    for (int k = 0; k < NN; k++) {
        float dk = sd[k];
        cnt += (dk < d2) || (dk == d2 && k < t);
    }
    if (cnt < KK) g_knn[n*KK + cnt] = t;
}

// -------- pc neighbor MLP (68->64->64->64, max, softmax, weighted sum) ------
__global__ void k_pcmlp(const float* __restrict__ wpts,
                        const float* __restrict__ w0, const float* __restrict__ b0,
                        const float* __restrict__ w1, const float* __restrict__ b1,
                        const float* __restrict__ w2, const float* __restrict__ b2) {
    extern __shared__ float sm[];
    float* sw0 = sm;             // 68*64 = 4352
    float* sw1 = sw0 + 4352;     // 4096
    float* sw2 = sw1 + 4096;     // 4096
    float* sb0 = sw2 + 4096; float* sb1 = sb0 + 64; float* sb2 = sb1 + 64;
    float* spts = sb2 + 64;      // 16*64
    float* sIn = spts + 1024;    // 68
    float* sh = sIn + 68; float* sh2 = sh + 64;
    float* swm = sh2 + 64;       // 16
    float* sred = swm + 16;      // 8
    int n = blockIdx.x, t = threadIdx.x;   // 64 threads
    for (int i = t; i < 4352; i += 64) sw0[i] = w0[i];
    for (int i = t; i < 4096; i += 64) sw1[i] = w1[i];
    for (int i = t; i < 4096; i += 64) sw2[i] = w2[i];
    sb0[t] = b0[t]; sb1[t] = b1[t]; sb2[t] = b2[t];
    __syncthreads();
    for (int r = 0; r < KK; r++) {
        int j = g_knn[n*KK + r];
        float pv = wpts[j*CC + t];
        spts[r*CC + t] = pv;
        sIn[t] = pv;
        if (t < 3) sIn[64+t] = g_xyz[j*3+t] - g_xyz[n*3+t];
        __syncthreads();
        if (t == 0) sIn[67] = sqrtf(sIn[64]*sIn[64] + sIn[65]*sIn[65] + sIn[66]*sIn[66]);
        __syncthreads();
        float a = sb0[t];
        #pragma unroll 4
        for (int i = 0; i < 68; i++) a += sIn[i]*sw0[i*64+t];
        sh[t] = fmaxf(a, 0.f);
        __syncthreads();
        a = sb1[t];
        #pragma unroll 8
        for (int i = 0; i < 64; i++) a += sh[i]*sw1[i*64+t];
        sh2[t] = fmaxf(a, 0.f);
        __syncthreads();
        a = sb2[t];
        #pragma unroll 8
        for (int i = 0; i < 64; i++) a += sh2[i]*sw2[i*64+t];
        a = fmaxf(a, 0.f);
        #pragma unroll
        for (int o = 16; o; o >>= 1) a = fmaxf(a, __shfl_xor_sync(0xffffffffu, a, o));
        if ((t & 31) == 0) sred[t >> 5] = a;
        __syncthreads();
        if (t == 0) swm[r] = fmaxf(sred[0], sred[1]);
        __syncthreads();
    }
    if (t == 0) {
        float mx = swm[0];
        for (int r = 1; r < KK; r++) mx = fmaxf(mx, swm[r]);
        float s = 0.f;
        for (int r = 0; r < KK; r++) { float e = expf(swm[r]-mx); swm[r] = e; s += e; }
        sred[0] = 1.f/s;
    }
    __syncthreads();
    float inv = sred[0], acc = 0.f;
    for (int r = 0; r < KK; r++) acc += swm[r]*spts[r*CC+t];
    float feat = acc*inv;
    __syncthreads();
    float ss = feat*feat;
    #pragma unroll
    for (int o = 16; o; o >>= 1) ss += __shfl_xor_sync(0xffffffffu, ss, o);
    if ((t & 31) == 0) sred[t >> 5] = ss;
    __syncthreads();
    float nrm = fmaxf(sqrtf(sred[0]+sred[1]), 1e-12f);
    g_pcnT[t*NN + n] = feat/nrm;
}

// ----------- image 3x3-patch MLP (67->64->64->64, softmax over 9) -----------
__global__ void k_imgmlp(const float* __restrict__ RF3, const float* __restrict__ RF3i,
                         const float* __restrict__ w0, const float* __restrict__ b0,
                         const float* __restrict__ w1, const float* __restrict__ b1,
                         const float* __restrict__ w2, const float* __restrict__ b2) {
    extern __shared__ float sm[];
    float* sw0 = sm;             // 67*64 = 4288
    float* sw1 = sw0 + 4288;     // 4096
    float* sw2 = sw1 + 4096;     // 4096
    float* sb0 = sw2 + 4096; float* sb1 = sb0 + 64; float* sb2 = sb1 + 64;
    float* spts = sb2 + 64;      // 9*64 = 576
    float* sidx = spts + 576;    // 28
    float* sh = sidx + 28; float* sh2 = sh + 64;
    float* swm = sh2 + 64;       // 12
    float* sred = swm + 12;      // 8
    int m = blockIdx.x, t = threadIdx.x;   // 64 threads
    int h0 = m >> 5, wc = m & 31;
    for (int i = t; i < 4288; i += 64) sw0[i] = w0[i];
    for (int i = t; i < 4096; i += 64) sw1[i] = w1[i];
    for (int i = t; i < 4096; i += 64) sw2[i] = w2[i];
    sb0[t] = b0[t]; sb1[t] = b1[t]; sb2[t] = b2[t];
    for (int p = 0; p < 9; p++) {
        int hh = h0 + p/3 - 1, ww = wc + p%3 - 1;
        bool inb = (hh >= 0) && (hh < 32) && (ww >= 0) && (ww < 32);
        int pix = hh*32 + ww;
        spts[p*CC + t] = inb ? RF3[t*MM + pix] : 0.f;
        if (t < 3) sidx[p*3 + t] = inb ? RF3i[t*MM + pix] : 0.f;
    }
    __syncthreads();
    for (int p = 0; p < 9; p++) {
        float a = sb0[t] + sidx[p*3+0]*sw0[t] + sidx[p*3+1]*sw0[64+t] + sidx[p*3+2]*sw0[128+t];
        #pragma unroll 8
        for (int c = 0; c < 64; c++) a += spts[p*CC+c]*sw0[(3+c)*64+t];
        sh[t] = fmaxf(a, 0.f);
        __syncthreads();
        a = sb1[t];
        #pragma unroll 8
        for (int i = 0; i < 64; i++) a += sh[i]*sw1[i*64+t];
        sh2[t] = fmaxf(a, 0.f);
        __syncthreads();
        a = sb2[t];
        #pragma unroll 8
        for (int i = 0; i < 64; i++) a += sh2[i]*sw2[i*64+t];
        a = fmaxf(a, 0.f);
        #pragma unroll
        for (int o = 16; o; o >>= 1) a = fmaxf(a, __shfl_xor_sync(0xffffffffu, a, o));
        if ((t & 31) == 0) sred[t >> 5] = a;
        __syncthreads();
        if (t == 0) swm[p] = fmaxf(sred[0], sred[1]);
        __syncthreads();
    }
    if (t == 0) {
        float mx = swm[0];
        for (int p = 1; p < 9; p++) mx = fmaxf(mx, swm[p]);
        float s = 0.f;
        for (int p = 0; p < 9; p++) { float e = expf(swm[p]-mx); swm[p] = e; s += e; }
        sred[0] = 1.f/s;
    }
    __syncthreads();
    float inv = sred[0], acc = 0.f;
    for (int p = 0; p < 9; p++) acc += swm[p]*spts[p*CC+t];
    float feat = acc*inv;
    __syncthreads();
    float ss = feat*feat;
    #pragma unroll
    for (int o = 16; o; o >>= 1) ss += __shfl_xor_sync(0xffffffffu, ss, o);
    if ((t & 31) == 0) sred[t >> 5] = ss;
    __syncthreads();
    float nrm = fmaxf(sqrtf(sred[0]+sred[1]), 1e-12f);
    g_imgn[m*CC + t] = feat/nrm;
}

// --------- per-n / per-m partials of the big layer-1 (A and C^T) ------------
__global__ void k_AC(const float* __restrict__ w10, const float* __restrict__ b10,
                     const float* __restrict__ wpts, const float* __restrict__ RF3) {
    __shared__ float sv[68];
    int b = blockIdx.x, t = threadIdx.x;   // 128 threads: t = j
    if (b < NN) {
        int n = b;
        if (t < 64) sv[t] = wpts[n*64 + t];
        if (t >= 64 && t < 67) sv[t] = g_xyz[n*3 + (t-64)];
        __syncthreads();
        float a = sv[64]*w10[t] + sv[65]*w10[128+t] + sv[66]*w10[256+t];
        #pragma unroll 8
        for (int c = 0; c < 64; c++) a += sv[c]*w10[(6+c)*128+t];
        g_A[n*128 + t] = a;
    } else {
        int m = b - NN;
        if (t < 64) sv[t] = RF3[t*MM + m];
        if (t >= 64 && t < 67) sv[t] = g_rfi[m*3 + (t-64)];
        __syncthreads();
        float a = b10[t] + sv[64]*w10[3*128+t] + sv[65]*w10[4*128+t] + sv[66]*w10[5*128+t];
        #pragma unroll 8
        for (int c = 0; c < 64; c++) a += sv[c]*w10[(70+c)*128+t];
        g_CmatT[t*MM + m] = a;
    }
}

// --------- fused big MLP: layer1 (factored) + 2 register-tiled GEMMs --------
__global__ __launch_bounds__(256) void k_big(const float* __restrict__ w10,
        const float* __restrict__ w11f, const float* __restrict__ b11f,
        const float* __restrict__ w12f, const float* __restrict__ b12f) {
    extern __shared__ float sm[];
    float* X1T = sm;                  // 128 x 132
    float* W11 = X1T + 128*132;       // 128 x 64
    float* X2T = W11 + 128*64;        // 64 x 132
    float* W12 = X2T + 64*132;        // 64 x 64
    float* sS  = W12 + 64*64;         // 4 x 128
    float* sA  = sS + 512;            // 128
    float* sW4 = sA + 128;            // 4 x 128
    float* zp  = sW4 + 512;           // 8 x 128
    float* B1  = zp + 1024;           // 64
    float* B2  = B1 + 64;             // 64
    int tid = threadIdx.x;
    int n  = blockIdx.x >> 3;
    int m0 = (blockIdx.x & 7) << 7;
    for (int i = tid; i < 128*64; i += 256) W11[i] = w11f[i];
    for (int i = tid; i < 64*64;  i += 256) W12[i] = w12f[i];
    if (tid < 64) { B1[tid] = b11f[tid]; B2[tid] = b12f[tid]; }
    if (tid < 128) {
        sA[tid]      = g_A[n*128 + tid];
        sW4[tid]     = w10[134*128 + tid];
        sW4[128+tid] = w10[135*128 + tid];
        sW4[256+tid] = w10[136*128 + tid];
        sW4[384+tid] = w10[137*128 + tid];
        int m = m0 + tid;
        float s1 = g_sim[m*NN + n];
        float s2 = g_sim2[m*NN + n];
        sS[tid]     = s1 / (g_colmax[n]  + 1e-6f);
        sS[128+tid] = s1 / (g_rowmax[m]  + 1e-10f);
        sS[256+tid] = s2 / (g_colmax2[n] + 1e-6f);
        sS[384+tid] = s2 / (g_rowmax2[m] + 1e-10f);
    }
    __syncthreads();
    // layer 1 -> X1T (transposed, padded)
    {
        int ml = tid & 127, jg = tid >> 7;
        float a0 = sS[ml], a1 = sS[128+ml], a2 = sS[256+ml], a3 = sS[384+ml];
        int mg = m0 + ml;
        #pragma unroll 4
        for (int it = 0; it < 64; it++) {
            int j = 2*it + jg;
            float v = sA[j] + g_CmatT[j*MM + mg]
                    + a0*sW4[j] + a1*sW4[128+j] + a2*sW4[256+j] + a3*sW4[384+j];
            X1T[j*132 + ml] = fmaxf(v, 0.f);
        }
    }
    __syncthreads();
    int mg = tid & 31, cg = tid >> 5;
    float acc[4][8];
    #pragma unroll
    for (int i = 0; i < 4; i++)
        #pragma unroll
        for (int jj = 0; jj < 8; jj++) acc[i][jj] = B1[cg*8 + jj];
    for (int k = 0; k < 128; k++) {
        float4 a  = *(const float4*)&X1T[k*132 + 4*mg];
        float4 b0 = *(const float4*)&W11[k*64 + 8*cg];
        float4 b1 = *(const float4*)&W11[k*64 + 8*cg + 4];
        float av[4] = {a.x, a.y, a.z, a.w};
        float bv[8] = {b0.x, b0.y, b0.z, b0.w, b1.x, b1.y, b1.z, b1.w};
        #pragma unroll
        for (int i = 0; i < 4; i++)
            #pragma unroll
            for (int jj = 0; jj < 8; jj++) acc[i][jj] += av[i]*bv[jj];
    }
    #pragma unroll
    for (int i = 0; i < 4; i++)
        #pragma unroll
        for (int jj = 0; jj < 8; jj++)
            X2T[(cg*8+jj)*132 + 4*mg + i] = fmaxf(acc[i][jj], 0.f);
    __syncthreads();
    #pragma unroll
    for (int i = 0; i < 4; i++)
        #pragma unroll
        for (int jj = 0; jj < 8; jj++) acc[i][jj] = B2[cg*8 + jj];
    for (int k = 0; k < 64; k++) {
        float4 a  = *(const float4*)&X2T[k*132 + 4*mg];
        float4 b0 = *(const float4*)&W12[k*64 + 8*cg];
        float4 b1 = *(const float4*)&W12[k*64 + 8*cg + 4];
        float av[4] = {a.x, a.y, a.z, a.w};
        float bv[8] = {b0.x, b0.y, b0.z, b0.w, b1.x, b1.y, b1.z, b1.w};
        #pragma unroll
        for (int i = 0; i < 4; i++)
            #pragma unroll
            for (int jj = 0; jj < 8; jj++) acc[i][jj] += av[i]*bv[jj];
    }
    // epilogue: relu, per-m channel max, write feats
    #pragma unroll
    for (int i = 0; i < 4; i++) {
        float mx = -1e30f;
        #pragma unroll
        for (int jj = 0; jj < 8; jj++) {
            acc[i][jj] = fmaxf(acc[i][jj], 0.f);
            mx = fmaxf(mx, acc[i][jj]);
        }
        int m = m0 + 4*mg + i;
        int p = (n*MM + m)*CC + 8*cg;
        float4 o0 = make_float4(acc[i][0], acc[i][1], acc[i][2], acc[i][3]);
        float4 o1 = make_float4(acc[i][4], acc[i][5], acc[i][6], acc[i][7]);
        *(float4*)&g_feats[p]   = o0;
        *(float4*)&g_feats[p+4] = o1;
        zp[cg*128 + 4*mg + i] = mx;
    }
    __syncthreads();
    if (tid < 128) {
        float z = zp[tid];
        #pragma unroll
        for (int c = 1; c < 8; c++) z = fmaxf(z, zp[c*128 + tid]);
        g_z[n*MM + m0 + tid] = z;
    }
}

// ------------- attention softmax + att/uv reductions + head MLP -------------
__global__ __launch_bounds__(256) void k_attn(const float* __restrict__ wm0, const float* __restrict__ bm0,
        const float* __restrict__ wm1, const float* __restrict__ bm1,
        const float* __restrict__ wm2, const float* __restrict__ bm2,
        float* __restrict__ out) {
    __shared__ float saw[1024];
    __shared__ float sred[256];
    __shared__ float satt[64];
    __shared__ float sh[128];
    int n = blockIdx.x, t = threadIdx.x;
    float v[4]; float mx = -1e30f;
    #pragma unroll
    for (int i = 0; i < 4; i++) { v[i] = g_z[n*MM + t + 256*i]; mx = fmaxf(mx, v[i]); }
    sred[t] = mx; __syncthreads();
    for (int s = 128; s > 0; s >>= 1) { if (t < s) sred[t] = fmaxf(sred[t], sred[t+s]); __syncthreads(); }
    float M = sred[0]; __syncthreads();
    float ls = 0.f;
    #pragma unroll
    for (int i = 0; i < 4; i++) { float e = expf(v[i]-M); saw[t + 256*i] = e; ls += e; }
    sred[t] = ls; __syncthreads();
    for (int s = 128; s > 0; s >>= 1) { if (t < s) sred[t] += sred[t+s]; __syncthreads(); }
    float inv = 1.f/sred[0]; __syncthreads();
    // att = sum_m aw * feats
    int c = t & 63, ml = t >> 6;
    float acc = 0.f;
    for (int m = ml; m < MM; m += 4) acc += saw[m]*g_feats[(n*MM + m)*CC + c];
    sred[t] = acc; __syncthreads();
    if (t < 64) satt[t] = (sred[t] + sred[64+t] + sred[128+t] + sred[192+t])*inv;
    // uv = sum_m aw * rfi (first two components)
    float a0 = 0.f, a1 = 0.f;
    for (int m = t; m < MM; m += 256) { float w = saw[m]; a0 += w*g_rfi[m*3]; a1 += w*g_rfi[m*3+1]; }
    __syncthreads();
    sred[t] = a0; __syncthreads();
    for (int s = 128; s > 0; s >>= 1) { if (t < s) sred[t] += sred[t+s]; __syncthreads(); }
    if (t == 0) g_uv[n*2] = sred[0]*inv;
    __syncthreads();
    sred[t] = a1; __syncthreads();
    for (int s = 128; s > 0; s >>= 1) { if (t < s) sred[t] += sred[t+s]; __syncthreads(); }
    if (t == 0) g_uv[n*2+1] = sred[0]*inv;
    __syncthreads();
    // head MLP: 64->64 relu -> 128 relu -> 2, softmax
    if (t < 64) {
        float a = bm0[t];
        #pragma unroll 8
        for (int k = 0; k < 64; k++) a += satt[k]*wm0[k*64+t];
        sh[t] = fmaxf(a, 0.f);
    }
    __syncthreads();
    if (t < 128) {
        float a = bm1[t];
        #pragma unroll 8
        for (int k = 0; k < 64; k++) a += sh[k]*wm1[k*128+t];
        sred[t] = fmaxf(a, 0.f);
    }
    __syncthreads();
    if (t == 0) {
        float l0 = bm2[0], l1 = bm2[1];
        for (int k = 0; k < 128; k++) { l0 += sred[k]*wm2[k*2]; l1 += sred[k]*wm2[k*2+1]; }
        float mm = fmaxf(l0, l1);
        float e0 = expf(l0-mm), e1 = expf(l1-mm), si = 1.f/(e0+e1);
        out[12 + 2*n] = e0*si;
        out[13 + 2*n] = e1*si;
        g_win[n] = (l1 > l0) ? 1.f : 0.f;
    }
}

// ------------------ weighted Kabsch / PnP with 3x3 SVD ----------------------
__device__ __forceinline__ float bred(float v, float* sred, int t) {
    sred[t] = v; __syncthreads();
    for (int s = 128; s > 0; s >>= 1) { if (t < s) sred[t] += sred[t+s]; __syncthreads(); }
    float r = sred[0]; __syncthreads();
    return r;
}

__global__ void k_pnp(float* __restrict__ out) {
    __shared__ float sred[256];
    int t = threadIdx.x;
    float w = g_win[t];
    float x0 = g_xyz[3*t], x1 = g_xyz[3*t+1], x2 = g_xyz[3*t+2];
    float u0 = g_uv[2*t], u1 = g_uv[2*t+1];
    float d0 = u0*x2, d1 = u1*x2, d2 = x2;
    float S = bred(w, sred, t);
    float wn = w/(S + 1e-8f);
    float sc0 = bred(wn*x0, sred, t), sc1 = bred(wn*x1, sred, t), sc2 = bred(wn*x2, sred, t);
    float dc0 = bred(wn*d0, sred, t), dc1 = bred(wn*d1, sred, t), dc2 = bred(wn*d2, sred, t);
    float a0 = x0-sc0, a1 = x1-sc1, a2 = x2-sc2;
    float e0 = d0-dc0, e1 = d1-dc1, e2 = d2-dc2;
    float Hm[9];
    Hm[0] = bred(wn*a0*e0, sred, t); Hm[1] = bred(wn*a0*e1, sred, t); Hm[2] = bred(wn*a0*e2, sred, t);
    Hm[3] = bred(wn*a1*e0, sred, t); Hm[4] = bred(wn*a1*e1, sred, t); Hm[5] = bred(wn*a1*e2, sred, t);
    Hm[6] = bred(wn*a2*e0, sred, t); Hm[7] = bred(wn*a2*e1, sred, t); Hm[8] = bred(wn*a2*e2, sred, t);
    if (t == 0) {
        double Hd[3][3] = {{Hm[0],Hm[1],Hm[2]},{Hm[3],Hm[4],Hm[5]},{Hm[6],Hm[7],Hm[8]}};
        double Bm[3][3], V[3][3] = {{1,0,0},{0,1,0},{0,0,1}};
        for (int i = 0; i < 3; i++)
            for (int j = 0; j < 3; j++) {
                double s = 0; for (int k = 0; k < 3; k++) s += Hd[k][i]*Hd[k][j];
                Bm[i][j] = s;
            }
        for (int sw = 0; sw < 50; sw++)
            for (int p = 0; p < 2; p++)
                for (int q = p+1; q < 3; q++) {
                    double apq = Bm[p][q];
                    if (fabs(apq) < 1e-300) continue;
                    double tau = (Bm[q][q]-Bm[p][p])/(2.0*apq);
                    double tt = (tau >= 0 ? 1.0 : -1.0)/(fabs(tau)+sqrt(1.0+tau*tau));
                    double c = 1.0/sqrt(1.0+tt*tt), s = tt*c;
                    for (int k = 0; k < 3; k++) {
                        double bkp = Bm[k][p], bkq = Bm[k][q];
                        Bm[k][p] = c*bkp - s*bkq; Bm[k][q] = s*bkp + c*bkq;
                    }
                    for (int k = 0; k < 3; k++) {
                        double bpk = Bm[p][k], bqk = Bm[q][k];
                        Bm[p][k] = c*bpk - s*bqk; Bm[q][k] = s*bpk + c*bqk;
                    }
                    for (int k = 0; k < 3; k++) {
                        double vkp = V[k][p], vkq = V[k][q];
                        V[k][p] = c*vkp - s*vkq; V[k][q] = s*vkp + c*vkq;
                    }
                }
        double lam[3] = {Bm[0][0], Bm[1][1], Bm[2][2]};
        int ord[3] = {0,1,2};
        for (int i = 0; i < 2; i++)
            for (int j = i+1; j < 3; j++)
                if (lam[ord[j]] > lam[ord[i]]) { int tmp = ord[i]; ord[i] = ord[j]; ord[j] = tmp; }
        double Vs[3][3], U[3][3];
        for (int k = 0; k < 3; k++)
            for (int i = 0; i < 3; i++) Vs[i][k] = V[i][ord[k]];
        for (int k = 0; k < 3; k++) {
            double u[3];
            for (int i = 0; i < 3; i++) {
                double s = 0; for (int j = 0; j < 3; j++) s += Hd[i][j]*Vs[j][k];
                u[i] = s;
            }
            double nm = sqrt(u[0]*u[0]+u[1]*u[1]+u[2]*u[2]);
            double ii = nm > 1e-300 ? 1.0/nm : 0.0;
            for (int i = 0; i < 3; i++) U[i][k] = u[i]*ii;
        }
        double detV = Vs[0][0]*(Vs[1][1]*Vs[2][2]-Vs[1][2]*Vs[2][1])
                    - Vs[0][1]*(Vs[1][0]*Vs[2][2]-Vs[1][2]*Vs[2][0])
                    + Vs[0][2]*(Vs[1][0]*Vs[2][1]-Vs[1][1]*Vs[2][0]);
        double detU = U[0][0]*(U[1][1]*U[2][2]-U[1][2]*U[2][1])
                    - U[0][1]*(U[1][0]*U[2][2]-U[1][2]*U[2][0])
                    + U[0][2]*(U[1][0]*U[2][1]-U[1][1]*U[2][0]);
        double dgn = detV*detU;
        double R[3][3];
        for (int i = 0; i < 3; i++)
            for (int j = 0; j < 3; j++)
                R[i][j] = Vs[i][0]*U[j][0] + Vs[i][1]*U[j][1] + dgn*Vs[i][2]*U[j][2];
        double sc[3] = {sc0, sc1, sc2}, dc[3] = {dc0, dc1, dc2};
        for (int i = 0; i < 3; i++) {
            for (int j = 0; j < 3; j++) out[i*3+j] = (float)R[i][j];
            double ti = dc[i];
            for (int j = 0; j < 3; j++) ti -= R[i][j]*sc[j];
            out[9+i] = (float)ti;
        }
    }
}

// ----------------------------------- launch ---------------------------------
extern "C" void kernel_launch(void* const* d_in, const int* in_sizes, int n_in,
                              void* d_out, int out_size) {
    const float* wxyz = (const float*)d_in[0];
    const float* wpts = (const float*)d_in[1];
    const float* RF3  = (const float*)d_in[2];
    const float* RF3i = (const float*)d_in[3];
    const float* lz   = (const float*)d_in[4];
    const float* w20 = (const float*)d_in[5];  const float* b20 = (const float*)d_in[6];
    const float* w21 = (const float*)d_in[7];  const float* b21 = (const float*)d_in[8];
    const float* w22 = (const float*)d_in[9];  const float* b22 = (const float*)d_in[10];
    const float* w30 = (const float*)d_in[11]; const float* b30 = (const float*)d_in[12];
    const float* w31 = (const float*)d_in[13]; const float* b31 = (const float*)d_in[14];
    const float* w32 = (const float*)d_in[15]; const float* b32 = (const float*)d_in[16];
    const float* w10 = (const float*)d_in[17]; const float* b10 = (const float*)d_in[18];
    const float* w11 = (const float*)d_in[19]; const float* b11 = (const float*)d_in[20];
    const float* w12 = (const float*)d_in[21]; const float* b12 = (const float*)d_in[22];
    const float* wm0 = (const float*)d_in[23]; const float* bm0 = (const float*)d_in[24];
    const float* wm1 = (const float*)d_in[25]; const float* bm1 = (const float*)d_in[26];
    const float* wm2 = (const float*)d_in[27]; const float* bm2 = (const float*)d_in[28];
    float* out = (float*)d_out;

    size_t pc_smem  = 13980u * sizeof(float);
    size_t img_smem = 13424u * sizeof(float);
    size_t big_smem = 39936u * sizeof(float);
    cudaFuncSetAttribute(k_pcmlp,  cudaFuncAttributeMaxDynamicSharedMemorySize, (int)pc_smem);
    cudaFuncSetAttribute(k_imgmlp, cudaFuncAttributeMaxDynamicSharedMemorySize, (int)img_smem);
    cudaFuncSetAttribute(k_big,    cudaFuncAttributeMaxDynamicSharedMemorySize, (int)big_smem);

    k_prep<<<NN+MM, 64>>>(wxyz, wpts, RF3, RF3i, lz);
    k_simmat<<<MM, NN>>>(0);
    k_colmax<<<NN, 256>>>(0);
    k_knn<<<NN, 256>>>();
    k_pcmlp<<<NN, 64, pc_smem>>>(wpts, w20, b20, w21, b21, w22, b22);
    k_imgmlp<<<MM, 64, img_smem>>>(RF3, RF3i, w30, b30, w31, b31, w32, b32);
    k_simmat<<<MM, NN>>>(1);
    k_colmax<<<NN, 256>>>(1);
    k_AC<<<NN+MM, 128>>>(w10, b10, wpts, RF3);
    k_big<<<2048, 256, big_smem>>>(w10, w11, b11, w12, b12);
    k_attn<<<NN, 256>>>(wm0, bm0, wm1, bm1, wm2, bm2, out);
    k_pnp<<<1, 256>>>(out);
}